// round 17
// baseline (speedup 1.0000x reference)
#include <cuda_runtime.h>
#include <cuda_fp16.h>

#define N_CELL  60000
#define N_GENE  4000
#define DIM     128
#define E_EDGES 1500000
#define EPS_BN  1e-5f

#define PADH 136   // half stride for As/Bs (17*8: ldmatrix-aligned)
#define GEMM_SMEM (2 * 128 * PADH * 2)     // As+Bs fp16
#define NB_OUT ((N_CELL + 127) / 128)      // 469 blocks for out-GEMM
#define NB_Y   ((N_GENE + 127) / 128)      // 32 blocks for y-GEMM

#define G_CSR   296                        // 2 blocks/SM -> co-resident (148 SMs)
#define SCAN_B2 ((N_CELL + 255) / 256)     // 235 scan blocks of 256 cells
#define G_AGG   296
#define CPW     8
#define NTILE   ((N_CELL + 63) / 64)       // 938 cell-tiles of 64

// ---------------- scratch (static __device__, zero-initialized at load) ------------
__device__ int    g_hist[N_CELL];
__device__ int    g_off [N_CELL + 1];
__device__ int    g_rank[E_EDGES];
__device__ int    g_pub [256];             // decoupled-lookback: (aggregate+1) or 0
__device__ int    g_csr [E_EDGES];
__device__ int    g_bar1;                  // grid barrier counters (self-resetting)
__device__ int    g_bar2;
__device__ __half g_y   [(size_t)N_GENE * DIM];   // fp16(x_gene @ Wl)
__device__ float  g_colsum[DIM];
__device__ float  g_colsq [DIM];

// ---------------- grid barrier (all blocks co-resident by construction) ------------
__device__ __forceinline__ void barwait(int* cnt, int target) {
    __syncthreads();
    if (threadIdx.x == 0) {
        __threadfence();
        atomicAdd(cnt, 1);
        while (atomicAdd(cnt, 0) < target) { }
        __threadfence();
    }
    __syncthreads();
}

// ---------------- 1: fused CSR build: hist+rank | scan | place ----------------------
__global__ __launch_bounds__(256, 2) void k_csr(
    const int4* __restrict__ src, const int4* __restrict__ dst,
    int4* __restrict__ rank)
{
    int bid = blockIdx.x, tid = threadIdx.x;
    int lane = tid & 31, wid = tid >> 5;

    // ---- phase 1: histogram + per-edge rank ----
    for (int i = bid * 256 + tid; i < E_EDGES / 4; i += G_CSR * 256) {
        int4 d = __ldg(&dst[i]);
        int4 r;
        r.x = atomicAdd(&g_hist[d.x], 1);
        r.y = atomicAdd(&g_hist[d.y], 1);
        r.z = atomicAdd(&g_hist[d.z], 1);
        r.w = atomicAdd(&g_hist[d.w], 1);
        rank[i] = r;
    }
    barwait(&g_bar1, G_CSR);

    // ---- phase 2: decoupled-lookback scan (blocks 0..SCAN_B2-1, 256 cells each) ----
    if (bid < SCAN_B2) {
        __shared__ int wsum[8];
        __shared__ int exc;
        if (tid == 0) exc = 0;
        int i = bid * 256 + tid;
        int v = 0;
        if (i < N_CELL) {
            v = g_hist[i];
            g_hist[i] = 0;     // self-clean for next replay
        }
        int x = v;
        #pragma unroll
        for (int o = 1; o < 32; o <<= 1) {
            int y = __shfl_up_sync(0xffffffffu, x, o);
            if (lane >= o) x += y;
        }
        if (lane == 31) wsum[wid] = x;
        __syncthreads();
        if (wid == 0) {
            int w = (lane < 8) ? wsum[lane] : 0;
            #pragma unroll
            for (int o = 1; o < 8; o <<= 1) {
                int y = __shfl_up_sync(0xffffffffu, w, o);
                if (lane >= o) w += y;
            }
            if (lane < 8) wsum[lane] = w;
        }
        __syncthreads();
        int incl = x + (wid ? wsum[wid - 1] : 0);

        if (tid == 255) atomicExch(&g_pub[bid], incl + 1);
        if (tid < bid) {
            int p;
            do { p = atomicAdd(&g_pub[tid], 0); } while (p == 0);
            atomicAdd(&exc, p - 1);
        }
        __syncthreads();
        if (i < N_CELL) {
            g_off[i + 1] = incl + exc;
            if (i == 0) g_off[0] = 0;
        }
    }
    barwait(&g_bar1, 2 * G_CSR);

    // ---- phase 3: cleanup + atomic-free placement ----
    if (bid == 0) {
        g_pub[tid] = 0;
        if (tid < DIM) { g_colsum[tid] = 0.f; g_colsq[tid] = 0.f; }
    }
    for (int i = bid * 256 + tid; i < E_EDGES / 4; i += G_CSR * 256) {
        int4 s = __ldg(&src[i]);
        int4 d = __ldg(&dst[i]);
        int4 r = __ldg(&rank[i]);
        g_csr[__ldg(&g_off[d.x]) + r.x] = s.x;
        g_csr[__ldg(&g_off[d.y]) + r.y] = s.y;
        g_csr[__ldg(&g_off[d.z]) + r.z] = s.z;
        g_csr[__ldg(&g_off[d.w]) + r.w] = s.w;
    }
    // exit arrival; last block resets the counter for the next graph replay
    __syncthreads();
    if (tid == 0) {
        int a = atomicAdd(&g_bar1, 1);
        if (a == 3 * G_CSR - 1) atomicExch(&g_bar1, 0);
    }
}

// ---------------- 2: unified tensor-core GEMM (R12 form) ---------------------------
__device__ __forceinline__ unsigned su32(const void* p) {
    return (unsigned)__cvta_generic_to_shared(p);
}
__device__ __forceinline__ void ldsm4(unsigned a, unsigned& r0, unsigned& r1,
                                      unsigned& r2, unsigned& r3) {
    asm volatile("ldmatrix.sync.aligned.m8n8.x4.shared.b16 {%0,%1,%2,%3}, [%4];"
                 : "=r"(r0), "=r"(r1), "=r"(r2), "=r"(r3) : "r"(a));
}
__device__ __forceinline__ void ldsm4t(unsigned a, unsigned& r0, unsigned& r1,
                                       unsigned& r2, unsigned& r3) {
    asm volatile("ldmatrix.sync.aligned.m8n8.x4.trans.shared.b16 {%0,%1,%2,%3}, [%4];"
                 : "=r"(r0), "=r"(r1), "=r"(r2), "=r"(r3) : "r"(a));
}
__device__ __forceinline__ void mma16816(float* d, const unsigned* a, const unsigned* b) {
    asm volatile(
        "mma.sync.aligned.m16n8k16.row.col.f32.f16.f16.f32 "
        "{%0,%1,%2,%3}, {%4,%5,%6,%7}, {%8,%9}, {%0,%1,%2,%3};"
        : "+f"(d[0]), "+f"(d[1]), "+f"(d[2]), "+f"(d[3])
        : "r"(a[0]), "r"(a[1]), "r"(a[2]), "r"(a[3]), "r"(b[0]), "r"(b[1]));
}

__global__ __launch_bounds__(256, 2) void k_gemm_both(
    const float* __restrict__ x_cell,
    const float* __restrict__ Wr,
    const float* __restrict__ x_gene,
    const float* __restrict__ Wl,
    float* __restrict__ out)
{
    extern __shared__ char smem[];
    __half* As = (__half*)smem;                // [128][PADH]
    __half* Bs = (__half*)smem + 128 * PADH;   // [128][PADH], stored [k][n]

    int bid = blockIdx.x;
    bool isY = (bid >= NB_OUT);
    const float* A = isY ? x_gene : x_cell;
    const float* B = isY ? Wl : Wr;
    int M  = isY ? N_GENE : N_CELL;
    int m0 = (isY ? bid - NB_OUT : bid) * 128;

    int tid  = threadIdx.x;
    int warp = tid >> 5, lane = tid & 31;
    int wm = warp & 3, wn = warp >> 2;

    #pragma unroll
    for (int it = 0; it < 16; it++) {
        int idx = tid + it * 256;
        int row = idx >> 5, q = idx & 31;
        float4 v = {0.f, 0.f, 0.f, 0.f};
        int gm = m0 + row;
        if (gm < M) v = *(const float4*)&A[(size_t)gm * DIM + q * 4];
        *(__half2*)&As[row * PADH + q * 4]     = __floats2half2_rn(v.x, v.y);
        *(__half2*)&As[row * PADH + q * 4 + 2] = __floats2half2_rn(v.z, v.w);
    }
    #pragma unroll
    for (int it = 0; it < 16; it++) {
        int idx = tid + it * 256;
        int k = idx >> 5, n4 = idx & 31;
        float4 v = *(const float4*)&B[(size_t)k * DIM + n4 * 4];
        *(__half2*)&Bs[k * PADH + n4 * 4]     = __floats2half2_rn(v.x, v.y);
        *(__half2*)&Bs[k * PADH + n4 * 4 + 2] = __floats2half2_rn(v.z, v.w);
    }
    __syncthreads();

    float acc[2][8][4];
    #pragma unroll
    for (int tm = 0; tm < 2; tm++)
        #pragma unroll
        for (int tn = 0; tn < 8; tn++)
            #pragma unroll
            for (int j = 0; j < 4; j++) acc[tm][tn][j] = 0.f;

    #pragma unroll
    for (int ks = 0; ks < 8; ks++) {
        unsigned a[2][4], b[8][2];
        #pragma unroll
        for (int tm = 0; tm < 2; tm++) {
            unsigned addr = su32(&As[(wm * 32 + tm * 16 + (lane & 15)) * PADH
                                     + ks * 16 + (lane >> 4) * 8]);
            ldsm4(addr, a[tm][0], a[tm][1], a[tm][2], a[tm][3]);
        }
        #pragma unroll
        for (int tp = 0; tp < 4; tp++) {
            unsigned addr = su32(&Bs[(ks * 16 + (lane & 15)) * PADH
                                     + wn * 64 + tp * 16 + (lane >> 4) * 8]);
            ldsm4t(addr, b[tp * 2][0], b[tp * 2][1], b[tp * 2 + 1][0], b[tp * 2 + 1][1]);
        }
        #pragma unroll
        for (int tm = 0; tm < 2; tm++)
            #pragma unroll
            for (int tn = 0; tn < 8; tn++)
                mma16816(acc[tm][tn], a[tm], b[tn]);
    }

    if (!isY) {
        #pragma unroll
        for (int tm = 0; tm < 2; tm++) {
            int r0 = m0 + wm * 32 + tm * 16 + (lane >> 2);
            #pragma unroll
            for (int tn = 0; tn < 8; tn++) {
                int c = wn * 64 + tn * 8 + (lane & 3) * 2;
                if (r0 < N_CELL)
                    *(float2*)&out[(size_t)r0 * DIM + c] =
                        make_float2(acc[tm][tn][0], acc[tm][tn][1]);
                if (r0 + 8 < N_CELL)
                    *(float2*)&out[(size_t)(r0 + 8) * DIM + c] =
                        make_float2(acc[tm][tn][2], acc[tm][tn][3]);
            }
        }
    } else {
        #pragma unroll
        for (int tm = 0; tm < 2; tm++) {
            int r0 = m0 + wm * 32 + tm * 16 + (lane >> 2);
            #pragma unroll
            for (int tn = 0; tn < 8; tn++) {
                int c = wn * 64 + tn * 8 + (lane & 3) * 2;
                if (r0 < N_GENE)
                    *(__half2*)&g_y[(size_t)r0 * DIM + c] =
                        __floats2half2_rn(acc[tm][tn][0], acc[tm][tn][1]);
                if (r0 + 8 < N_GENE)
                    *(__half2*)&g_y[(size_t)(r0 + 8) * DIM + c] =
                        __floats2half2_rn(acc[tm][tn][2], acc[tm][tn][3]);
            }
        }
    }
}

// ---------------- 3: persistent gather+BN | grid barrier | normalize ---------------
__global__ __launch_bounds__(256, 2) void k_aggbn_norm(float* __restrict__ out) {
    __shared__ float red[2][8][DIM];
    int tid  = threadIdx.x;
    int warp = tid >> 5, lane = tid & 31;
    const uint2* yv = (const uint2*)g_y;

    float s[4] = {0.f, 0.f, 0.f, 0.f};
    float q[4] = {0.f, 0.f, 0.f, 0.f};

    // ---- phase 1: persistent over the 938 cell-tiles (R12 aggbn body) ----
    for (int blk = blockIdx.x; blk < NTILE; blk += G_AGG) {
        int cell0 = (blk * 8 + warp) * CPW;
        for (int ci = 0; ci < CPW; ci++) {
            int gm = cell0 + ci;
            if (gm >= N_CELL) break;
            int es = g_off[gm], ee = g_off[gm + 1];

            float ax0=0.f, ax1=0.f, ax2=0.f, ax3=0.f;
            float bx0=0.f, bx1=0.f, bx2=0.f, bx3=0.f;
            float cx0=0.f, cx1=0.f, cx2=0.f, cx3=0.f;
            float dx0=0.f, dx1=0.f, dx2=0.f, dx3=0.f;
            int j = es;
            for (; j + 3 < ee; j += 4) {
                int g0 = __ldg(&g_csr[j]);
                int g1 = __ldg(&g_csr[j + 1]);
                int g2 = __ldg(&g_csr[j + 2]);
                int g3 = __ldg(&g_csr[j + 3]);
                uint2 u0 = __ldg(&yv[(size_t)g0 * 32 + lane]);
                uint2 u1 = __ldg(&yv[(size_t)g1 * 32 + lane]);
                uint2 u2 = __ldg(&yv[(size_t)g2 * 32 + lane]);
                uint2 u3 = __ldg(&yv[(size_t)g3 * 32 + lane]);
                float2 p, r;
                p = __half22float2(*(__half2*)&u0.x); r = __half22float2(*(__half2*)&u0.y);
                ax0 += p.x; ax1 += p.y; ax2 += r.x; ax3 += r.y;
                p = __half22float2(*(__half2*)&u1.x); r = __half22float2(*(__half2*)&u1.y);
                bx0 += p.x; bx1 += p.y; bx2 += r.x; bx3 += r.y;
                p = __half22float2(*(__half2*)&u2.x); r = __half22float2(*(__half2*)&u2.y);
                cx0 += p.x; cx1 += p.y; cx2 += r.x; cx3 += r.y;
                p = __half22float2(*(__half2*)&u3.x); r = __half22float2(*(__half2*)&u3.y);
                dx0 += p.x; dx1 += p.y; dx2 += r.x; dx3 += r.y;
            }
            for (; j < ee; j++) {
                int g0 = __ldg(&g_csr[j]);
                uint2 u0 = __ldg(&yv[(size_t)g0 * 32 + lane]);
                float2 p = __half22float2(*(__half2*)&u0.x);
                float2 r = __half22float2(*(__half2*)&u0.y);
                ax0 += p.x; ax1 += p.y; ax2 += r.x; ax3 += r.y;
            }
            float inv = 1.f / (float)max(ee - es, 1);
            float4 v = *(float4*)&out[(size_t)gm * DIM + lane * 4];
            v.x = fmaf(ax0 + bx0 + cx0 + dx0, inv, v.x);
            v.y = fmaf(ax1 + bx1 + cx1 + dx1, inv, v.y);
            v.z = fmaf(ax2 + bx2 + cx2 + dx2, inv, v.z);
            v.w = fmaf(ax3 + bx3 + cx3 + dx3, inv, v.w);
            *(float4*)&out[(size_t)gm * DIM + lane * 4] = v;
            s[0] += v.x; q[0] += v.x * v.x;
            s[1] += v.y; q[1] += v.y * v.y;
            s[2] += v.z; q[2] += v.z * v.z;
            s[3] += v.w; q[3] += v.w * v.w;
        }
    }

    // single per-block reduction of accumulated BN partials
    #pragma unroll
    for (int c = 0; c < 4; c++) {
        red[0][warp][lane * 4 + c] = s[c];
        red[1][warp][lane * 4 + c] = q[c];
    }
    __syncthreads();
    if (tid < DIM) {
        float ss = 0.f, qq = 0.f;
        #pragma unroll
        for (int r = 0; r < 8; r++) { ss += red[0][r][tid]; qq += red[1][r][tid]; }
        atomicAdd(&g_colsum[tid], ss);
        atomicAdd(&g_colsq[tid], qq);
    }

    barwait(&g_bar2, G_AGG);

    // ---- phase 2: grid-stride normalize in place ----
    const int total = N_CELL * DIM / 4;
    const float invN = 1.f / (float)N_CELL;
    for (int i = blockIdx.x * 256 + tid; i < total; i += G_AGG * 256) {
        int c = (i & 31) * 4;
        float mu0 = g_colsum[c + 0] * invN, mu1 = g_colsum[c + 1] * invN;
        float mu2 = g_colsum[c + 2] * invN, mu3 = g_colsum[c + 3] * invN;
        float rs0 = rsqrtf(g_colsq[c + 0] * invN - mu0 * mu0 + EPS_BN);
        float rs1 = rsqrtf(g_colsq[c + 1] * invN - mu1 * mu1 + EPS_BN);
        float rs2 = rsqrtf(g_colsq[c + 2] * invN - mu2 * mu2 + EPS_BN);
        float rs3 = rsqrtf(g_colsq[c + 3] * invN - mu3 * mu3 + EPS_BN);
        float4 v = ((float4*)out)[i];
        v.x = (v.x - mu0) * rs0;
        v.y = (v.y - mu1) * rs1;
        v.z = (v.z - mu2) * rs2;
        v.w = (v.w - mu3) * rs3;
        ((float4*)out)[i] = v;
    }
    // exit arrival; last block resets the counter for the next graph replay
    __syncthreads();
    if (tid == 0) {
        int a = atomicAdd(&g_bar2, 1);
        if (a == 2 * G_AGG - 1) atomicExch(&g_bar2, 0);
    }
}

// ---------------- launch (two-stream fork/join inside graph capture) ----------------
extern "C" void kernel_launch(void* const* d_in, const int* in_sizes, int n_in,
                              void* d_out, int out_size) {
    const float* x_cell = (const float*)d_in[0];
    const float* x_gene = (const float*)d_in[1];
    const float* Wl_gc  = (const float*)d_in[2];
    const float* Wr_gc  = (const float*)d_in[4];
    const int* gc_src = (const int*)d_in[8];
    const int* gc_dst = (const int*)d_in[9];
    float* out = (float*)d_out;

    const float* Wl = Wl_gc + DIM * DIM;   // layer L-1 = 1
    const float* Wr = Wr_gc + DIM * DIM;

    static cudaStream_t sA = nullptr, sB = nullptr;
    static cudaEvent_t  e0 = nullptr, eB = nullptr, eA = nullptr;
    if (!sA) {
        cudaStreamCreateWithFlags(&sA, cudaStreamNonBlocking);
        cudaStreamCreateWithFlags(&sB, cudaStreamNonBlocking);
        cudaEventCreateWithFlags(&e0, cudaEventDisableTiming);
        cudaEventCreateWithFlags(&eB, cudaEventDisableTiming);
        cudaEventCreateWithFlags(&eA, cudaEventDisableTiming);
        cudaFuncSetAttribute(k_gemm_both,
                             cudaFuncAttributeMaxDynamicSharedMemorySize, GEMM_SMEM);
    }

    int* g_rank_p; cudaGetSymbolAddress((void**)&g_rank_p, g_rank);

    // fork from the capture-origin (legacy) stream
    cudaEventRecord(e0, (cudaStream_t)0);
    cudaStreamWaitEvent(sA, e0, 0);
    cudaStreamWaitEvent(sB, e0, 0);

    // chain A: single persistent CSR-build kernel
    k_csr<<<G_CSR, 256, 0, sA>>>((const int4*)gc_src, (const int4*)gc_dst,
                                 (int4*)g_rank_p);

    // chain B: both GEMMs fused into one tensor-core kernel
    k_gemm_both<<<NB_OUT + NB_Y, 256, GEMM_SMEM, sB>>>(x_cell, Wr, x_gene, Wl, out);
    cudaEventRecord(eB, sB);

    // join: aggbn_norm needs CSR + stats zeroed (sA), g_y and out (sB)
    cudaStreamWaitEvent(sA, eB, 0);
    k_aggbn_norm<<<G_AGG, 256, 0, sA>>>(out);

    // join back into the capture-origin stream
    cudaEventRecord(eA, sA);
    cudaStreamWaitEvent((cudaStream_t)0, eA, 0);
}